// round 9
// baseline (speedup 1.0000x reference)
#include <cuda_runtime.h>

#define SLOPE 0.3f
#define ATTN_SCALE 0.17677669529663687f   // 32^-0.5
#define LN_EPS 1e-3f

// ---- scratch (no allocs allowed) -------------------------------------------
__device__ float g_bias[4096];        // bias_table[rel_idx]  (64x64)
__device__ float g_h[67108864];       // (2*512*512, 128) hidden scratch, 256MB

// ---- packed f32x2 helpers ----------------------------------------------------
__device__ __forceinline__ unsigned long long pk2(float a, float b) {
    unsigned long long r;
    asm("mov.b64 %0, {%1, %2};" : "=l"(r)
        : "r"(__float_as_uint(a)), "r"(__float_as_uint(b)));
    return r;
}
__device__ __forceinline__ void upk2(unsigned long long v, float& a, float& b) {
    unsigned int x, y;
    asm("mov.b64 {%0, %1}, %2;" : "=r"(x), "=r"(y) : "l"(v));
    a = __uint_as_float(x); b = __uint_as_float(y);
}
__device__ __forceinline__ void fma2(unsigned long long& d,
                                     unsigned long long a, unsigned long long b) {
    asm("fma.rn.f32x2 %0, %1, %2, %0;" : "+l"(d) : "l"(a), "l"(b));
}
__device__ __forceinline__ float gelu_f(float z) {          // exact erf gelu
    return 0.5f * z * (1.0f + erff(z * 0.70710678118654752f));
}
__device__ __forceinline__ float leaky_f(float z) {
    return z >= 0.f ? z : SLOPE * z;
}

// ---- K0: gather relative-position bias --------------------------------------
__global__ void kbias(const float* __restrict__ table, const int* __restrict__ idx) {
    int i = blockIdx.x * 256 + threadIdx.x;
    if (i < 4096) g_bias[i] = table[idx[i]];
}

// ---- KA: fused LN1 + window attention + proj + residual  ->  x2 (= d_out) ---
// 1 block = 1 window (64 tokens), 1 thread = 1 token.
__global__ __launch_bounds__(64) void ka_attn(
    const float* __restrict__ x,
    const float* __restrict__ g1, const float* __restrict__ be1,
    const float* __restrict__ Wq, const float* __restrict__ bq,
    const float* __restrict__ Wkv, const float* __restrict__ bkv,
    const float* __restrict__ Wp, const float* __restrict__ bp,
    float* __restrict__ out)
{
    __shared__ __align__(16) float sWq[1024];
    __shared__ __align__(16) float sWkv[2048];
    __shared__ __align__(16) float sWp[1024];
    __shared__ __align__(16) float ks[2048];   // k transposed [c][m]
    __shared__ __align__(16) float vs[2048];   // v transposed [c][m]
    __shared__ float sbq[32], sbp[32], sg1[32], sbe1[32], sbkv[64];

    const int t = threadIdx.x;
    for (int i = t; i < 1024; i += 64) { sWq[i] = Wq[i]; sWp[i] = Wp[i]; }
    for (int i = t; i < 2048; i += 64) sWkv[i] = Wkv[i];
    if (t < 32) { sbq[t] = bq[t]; sbp[t] = bp[t]; sg1[t] = g1[t]; sbe1[t] = be1[t]; }
    if (t < 64) sbkv[t] = bkv[t];

    const int w  = blockIdx.x;
    const int b  = w >> 12;
    const int wy = (w >> 6) & 63;
    const int wx = w & 63;
    const int py = wy * 8 + (t >> 3);
    const int px = wx * 8 + (t & 7);
    const int base = (b * 262144 + py * 512 + px) * 32;

    // ---- LN1 ----
    float xn[32];
    {
        const float4* xp = reinterpret_cast<const float4*>(x + base);
        #pragma unroll
        for (int i = 0; i < 8; i++) {
            float4 v4 = xp[i];
            xn[4*i+0] = v4.x; xn[4*i+1] = v4.y; xn[4*i+2] = v4.z; xn[4*i+3] = v4.w;
        }
        float mu = 0.f;
        #pragma unroll
        for (int c = 0; c < 32; c++) mu += xn[c];
        mu *= 0.03125f;
        float var = 0.f;
        #pragma unroll
        for (int c = 0; c < 32; c++) { float d = xn[c] - mu; var += d * d; }
        float rs = rsqrtf(var * 0.03125f + LN_EPS);
        __syncthreads();   // weights staged
        #pragma unroll
        for (int c = 0; c < 32; c++) xn[c] = (xn[c] - mu) * rs * sg1[c] + sbe1[c];
    }

    // ---- q = leaky(xn @ Wq + bq) * SCALE ----
    float q[32];
    {
        unsigned long long acc[16];
        #pragma unroll
        for (int i = 0; i < 16; i++) acc[i] = 0ull;
        #pragma unroll 4
        for (int k = 0; k < 32; k++) {
            unsigned long long xk2 = pk2(xn[k], xn[k]);
            const ulonglong2* wr = reinterpret_cast<const ulonglong2*>(&sWq[k * 32]);
            #pragma unroll
            for (int j = 0; j < 8; j++) {
                ulonglong2 u = wr[j];
                fma2(acc[2*j+0], xk2, u.x);
                fma2(acc[2*j+1], xk2, u.y);
            }
        }
        #pragma unroll
        for (int i = 0; i < 16; i++) {
            float a0, a1; upk2(acc[i], a0, a1);
            q[2*i+0] = leaky_f(a0 + sbq[2*i+0]) * ATTN_SCALE;
            q[2*i+1] = leaky_f(a1 + sbq[2*i+1]) * ATTN_SCALE;
        }
    }

    // ---- k, v = leaky(xn @ Wkv + bkv), stored transposed [c][m] ----
    #pragma unroll
    for (int hh = 0; hh < 2; hh++) {
        unsigned long long acc[16];
        #pragma unroll
        for (int i = 0; i < 16; i++) acc[i] = 0ull;
        #pragma unroll 4
        for (int k = 0; k < 32; k++) {
            unsigned long long xk2 = pk2(xn[k], xn[k]);
            const ulonglong2* wr =
                reinterpret_cast<const ulonglong2*>(&sWkv[k * 64 + hh * 32]);
            #pragma unroll
            for (int j = 0; j < 8; j++) {
                ulonglong2 u = wr[j];
                fma2(acc[2*j+0], xk2, u.x);
                fma2(acc[2*j+1], xk2, u.y);
            }
        }
        float* dst = hh ? vs : ks;
        #pragma unroll
        for (int i = 0; i < 16; i++) {
            float a0, a1; upk2(acc[i], a0, a1);
            dst[(2*i+0) * 64 + t] = leaky_f(a0 + sbkv[hh * 32 + 2*i+0]);
            dst[(2*i+1) * 64 + t] = leaky_f(a1 + sbkv[hh * 32 + 2*i+1]);
        }
    }
    __syncthreads();

    // ---- scores: a[m] = q . k[:,m] + bias[t,m] ----
    float a[64];
    {
        unsigned long long aa[32];
        #pragma unroll
        for (int i = 0; i < 32; i++) aa[i] = 0ull;
        #pragma unroll 2
        for (int c = 0; c < 32; c++) {
            unsigned long long q2 = pk2(q[c], q[c]);
            const ulonglong2* kr = reinterpret_cast<const ulonglong2*>(&ks[c * 64]);
            #pragma unroll
            for (int j = 0; j < 16; j++) {
                ulonglong2 u = kr[j];
                fma2(aa[2*j+0], q2, u.x);
                fma2(aa[2*j+1], q2, u.y);
            }
        }
        const float* brow = &g_bias[t * 64];
        #pragma unroll
        for (int i = 0; i < 32; i++) {
            float a0, a1; upk2(aa[i], a0, a1);
            a[2*i+0] = a0 + brow[2*i+0];
            a[2*i+1] = a1 + brow[2*i+1];
        }
    }

    // ---- softmax ----
    float mx = a[0];
    #pragma unroll
    for (int m = 1; m < 64; m++) mx = fmaxf(mx, a[m]);
    float sum = 0.f;
    #pragma unroll
    for (int m = 0; m < 64; m++) { a[m] = __expf(a[m] - mx); sum += a[m]; }
    float inv = 1.f / sum;
    unsigned long long ap[32];
    #pragma unroll
    for (int i = 0; i < 32; i++) ap[i] = pk2(a[2*i+0] * inv, a[2*i+1] * inv);

    // ---- out = attn @ v ----
    float o[32];
    #pragma unroll 2
    for (int c = 0; c < 32; c++) {
        unsigned long long acc0 = 0ull, acc1 = 0ull;
        const ulonglong2* vr = reinterpret_cast<const ulonglong2*>(&vs[c * 64]);
        #pragma unroll
        for (int j = 0; j < 16; j++) {
            ulonglong2 u = vr[j];
            fma2(acc0, ap[2*j+0], u.x);
            fma2(acc1, ap[2*j+1], u.y);
        }
        float l0, h0, l1, h1;
        upk2(acc0, l0, h0); upk2(acc1, l1, h1);
        o[c] = (l0 + h0) + (l1 + h1);
    }

    // ---- proj + residual ----
    unsigned long long pa[16];
    #pragma unroll
    for (int i = 0; i < 16; i++) pa[i] = 0ull;
    #pragma unroll 4
    for (int c = 0; c < 32; c++) {
        unsigned long long o2 = pk2(o[c], o[c]);
        const ulonglong2* wr = reinterpret_cast<const ulonglong2*>(&sWp[c * 32]);
        #pragma unroll
        for (int j = 0; j < 8; j++) {
            ulonglong2 u = wr[j];
            fma2(pa[2*j+0], o2, u.x);
            fma2(pa[2*j+1], o2, u.y);
        }
    }
    const float4* xp2 = reinterpret_cast<const float4*>(x + base);
    float4* op = reinterpret_cast<float4*>(out + base);
    #pragma unroll
    for (int i = 0; i < 8; i++) {
        float4 xv = xp2[i];
        float a0, a1, b0, b1;
        upk2(pa[2*i+0], a0, a1);
        upk2(pa[2*i+1], b0, b1);
        float4 r;
        r.x = xv.x + a0 + sbp[4*i+0];
        r.y = xv.y + a1 + sbp[4*i+1];
        r.z = xv.z + b0 + sbp[4*i+2];
        r.w = xv.w + b1 + sbp[4*i+3];
        op[i] = r;
    }
}

// ---- KB1: LN2 + W1 + gelu  ->  g_h -------------------------------------------
__global__ __launch_bounds__(128) void kb1(
    const float* __restrict__ x2,
    const float* __restrict__ g2, const float* __restrict__ be2,
    const float* __restrict__ W1, const float* __restrict__ b1m)
{
    __shared__ __align__(16) float sW1[4096];
    __shared__ float sb1[128], sg[32], sb[32];
    const int t = threadIdx.x;
    for (int i = t; i < 4096; i += 128) sW1[i] = W1[i];
    sb1[t] = b1m[t];
    if (t < 32) { sg[t] = g2[t]; sb[t] = be2[t]; }

    const int tok = blockIdx.x * 128 + t;
    float y[32];
    const float4* xp = reinterpret_cast<const float4*>(x2 + tok * 32);
    #pragma unroll
    for (int i = 0; i < 8; i++) {
        float4 v4 = xp[i];
        y[4*i+0] = v4.x; y[4*i+1] = v4.y; y[4*i+2] = v4.z; y[4*i+3] = v4.w;
    }
    float mu = 0.f;
    #pragma unroll
    for (int c = 0; c < 32; c++) mu += y[c];
    mu *= 0.03125f;
    float var = 0.f;
    #pragma unroll
    for (int c = 0; c < 32; c++) { float d = y[c] - mu; var += d * d; }
    float rs = rsqrtf(var * 0.03125f + LN_EPS);
    __syncthreads();
    #pragma unroll
    for (int c = 0; c < 32; c++) y[c] = (y[c] - mu) * rs * sg[c] + sb[c];

    float4* hp = reinterpret_cast<float4*>(&g_h[(size_t)tok * 128]);
    #pragma unroll
    for (int p = 0; p < 4; p++) {
        unsigned long long acc[16];
        #pragma unroll
        for (int i = 0; i < 16; i++) acc[i] = 0ull;
        #pragma unroll 4
        for (int c = 0; c < 32; c++) {
            unsigned long long y2 = pk2(y[c], y[c]);
            const ulonglong2* wr =
                reinterpret_cast<const ulonglong2*>(&sW1[c * 128 + p * 32]);
            #pragma unroll
            for (int j = 0; j < 8; j++) {
                ulonglong2 u = wr[j];
                fma2(acc[2*j+0], y2, u.x);
                fma2(acc[2*j+1], y2, u.y);
            }
        }
        #pragma unroll
        for (int i = 0; i < 8; i++) {
            float v0, v1, v2, v3;
            upk2(acc[2*i+0], v0, v1);
            upk2(acc[2*i+1], v2, v3);
            int jb = p * 32 + 4 * i;
            float4 r;
            r.x = gelu_f(v0 + sb1[jb+0]);
            r.y = gelu_f(v1 + sb1[jb+1]);
            r.z = gelu_f(v2 + sb1[jb+2]);
            r.w = gelu_f(v3 + sb1[jb+3]);
            hp[p * 8 + i] = r;
        }
    }
}

// ---- KB2: depthwise 3x3 + gelu + W2 + residual  ->  d_out (in place) ---------
__global__ __launch_bounds__(256) void kb2(
    const float* __restrict__ dwk, const float* __restrict__ dwb,
    const float* __restrict__ W2, const float* __restrict__ b2m,
    float* __restrict__ out)
{
    __shared__ float tile[18 * 18 * 17 + 8];   // 16 ch/chunk, stride-17 padded
    __shared__ __align__(16) float sW2[4096];
    __shared__ float sk[1152], skb[128], sb2[32];

    const int t = threadIdx.x;
    for (int i = t; i < 4096; i += 256) sW2[i] = W2[i];
    for (int i = t; i < 1152; i += 256) sk[i] = dwk[i];
    if (t < 128) skb[t] = dwb[t];
    if (t < 32) sb2[t] = b2m[t];

    const int bb  = blockIdx.x;
    const int b   = bb >> 10;                 // 2 * 32 * 32 blocks
    const int ty0 = ((bb >> 5) & 31) * 16;
    const int tx0 = (bb & 31) * 16;
    const int ly = t >> 4, lx = t & 15;
    const int gy = ty0 + ly, gx = tx0 + lx;
    const int plane = b * 262144;

    unsigned long long acc[16];
    #pragma unroll
    for (int i = 0; i < 16; i++) acc[i] = 0ull;

    for (int chunk = 0; chunk < 8; chunk++) {
        __syncthreads();
        for (int i = t; i < 1296; i += 256) {     // 324 positions x 4 float4
            int pos = i >> 2, sub = i & 3;
            int ry = pos / 18, rx = pos - ry * 18;
            int yy = ty0 + ry - 1, xx = tx0 + rx - 1;
            float4 v4 = make_float4(0.f, 0.f, 0.f, 0.f);
            if (yy >= 0 && yy < 512 && xx >= 0 && xx < 512) {
                v4 = *reinterpret_cast<const float4*>(
                    &g_h[(size_t)(plane + yy * 512 + xx) * 128 + chunk * 16 + sub * 4]);
            }
            float* dst = &tile[pos * 17 + sub * 4];
            dst[0] = v4.x; dst[1] = v4.y; dst[2] = v4.z; dst[3] = v4.w;
        }
        __syncthreads();

        #pragma unroll 4
        for (int cc = 0; cc < 16; cc++) {
            int c = chunk * 16 + cc;
            float s = 0.f;
            #pragma unroll
            for (int ky = 0; ky < 3; ky++)
                #pragma unroll
                for (int kx = 0; kx < 3; kx++)
                    s += tile[((ly + ky) * 18 + (lx + kx)) * 17 + cc] *
                         sk[(ky * 3 + kx) * 128 + c];
            s = gelu_f(s + skb[c]);
            unsigned long long s2 = pk2(s, s);
            const ulonglong2* wr = reinterpret_cast<const ulonglong2*>(&sW2[c * 32]);
            #pragma unroll
            for (int j = 0; j < 8; j++) {
                ulonglong2 u = wr[j];
                fma2(acc[2*j+0], s2, u.x);
                fma2(acc[2*j+1], s2, u.y);
            }
        }
    }

    const int base = (plane + gy * 512 + gx) * 32;
    #pragma unroll
    for (int i = 0; i < 8; i++) {
        float4 xv = *reinterpret_cast<const float4*>(out + base + 4 * i);
        float a0, a1, b0, b1;
        upk2(acc[2*i+0], a0, a1);
        upk2(acc[2*i+1], b0, b1);
        float4 r;
        r.x = xv.x + a0 + sb2[4*i+0];
        r.y = xv.y + a1 + sb2[4*i+1];
        r.z = xv.z + b0 + sb2[4*i+2];
        r.w = xv.w + b1 + sb2[4*i+3];
        *reinterpret_cast<float4*>(out + base + 4 * i) = r;
    }
}

// ---- launch -------------------------------------------------------------------
extern "C" void kernel_launch(void* const* d_in, const int* in_sizes, int n_in,
                              void* d_out, int out_size) {
    const float* x          = (const float*)d_in[0];
    const float* g1         = (const float*)d_in[1];
    const float* beta1      = (const float*)d_in[2];
    const float* Wq         = (const float*)d_in[3];
    const float* bq         = (const float*)d_in[4];
    const float* Wkv        = (const float*)d_in[5];
    const float* bkv        = (const float*)d_in[6];
    const float* bias_table = (const float*)d_in[7];
    const float* Wp         = (const float*)d_in[8];
    const float* bp         = (const float*)d_in[9];
    const float* g2         = (const float*)d_in[10];
    const float* beta2      = (const float*)d_in[11];
    const float* W1         = (const float*)d_in[12];
    const float* b1m        = (const float*)d_in[13];
    const float* dw_k       = (const float*)d_in[14];
    const float* dw_b       = (const float*)d_in[15];
    const float* W2         = (const float*)d_in[16];
    const float* b2m        = (const float*)d_in[17];
    const int*   rel_idx    = (const int*)d_in[18];
    float* out = (float*)d_out;

    kbias<<<16, 256>>>(bias_table, rel_idx);
    ka_attn<<<8192, 64>>>(x, g1, beta1, Wq, bq, Wkv, bkv, Wp, bp, out);
    kb1<<<4096, 128>>>(out, g2, beta2, W1, b1m);
    kb2<<<2048, 256>>>(dw_k, dw_b, W2, b2m, out);
}